// round 16
// baseline (speedup 1.0000x reference)
#include <cuda_runtime.h>
#include <cstdint>

#define BATCH 512
#define CIN   12
#define LIN   5000
#define C1    32
#define K1    50
#define S1    10
#define L1    496
#define C2    32
#define K2    25
#define S2    5
#define L2    95
#define LAT   32
#define HID   64
#define TSTEPS L2
#define EPS   1e-5f

#define NCHUNK 75          // K = 600 = 5(a) * 120(cb), 8 per chunk
#define ZW    72           // z row stride (conflict-free: 72 mod 32 = 8)
#define ZROWS 120

// ---------------- device scratch (no allocation allowed) ----------------
// conv1 B fragments: [chunk(75)][ntile(4)][lane(32)] = {bhi0,bhi1,blo0,blo1}
__device__ __align__(16) uint4 g_B[NCHUNK * 4 * 32];
// conv2 weights: [ci][tap(25)][oc(32)] float
__device__ __align__(16) float g_w2s[C2 * 25 * C2];
__device__ float g_y1[BATCH * C1 * L1];
__device__ float g_y2[BATCH * C2 * L2];
__device__ float g_xt[TSTEPS * BATCH * LAT];
__device__ float g_stats1[64];
__device__ float g_stats2[64];

__device__ __forceinline__ float warp_sum(float v) {
    #pragma unroll
    for (int o = 16; o; o >>= 1) v += __shfl_xor_sync(0xffffffffu, v, o);
    return v;
}
__device__ __forceinline__ uint32_t f2tf32(float f) {
    uint32_t r;
    asm("cvt.rna.tf32.f32 %0, %1;" : "=r"(r) : "f"(f));
    return r;
}
__device__ __forceinline__ void tf32split(float x, uint32_t& hi, uint32_t& lo) {
    hi = f2tf32(x);
    lo = f2tf32(x - __uint_as_float(hi));
}
__device__ __forceinline__ void mma_tf32(float* d,
    uint32_t a0, uint32_t a1, uint32_t a2, uint32_t a3,
    uint32_t b0, uint32_t b1)
{
    asm volatile(
        "mma.sync.aligned.m16n8k8.row.col.f32.tf32.tf32.f32 "
        "{%0,%1,%2,%3},{%4,%5,%6,%7},{%8,%9},{%0,%1,%2,%3};"
        : "+f"(d[0]), "+f"(d[1]), "+f"(d[2]), "+f"(d[3])
        : "r"(a0), "r"(a1), "r"(a2), "r"(a3), "r"(b0), "r"(b1));
}

// ---------------- kernel 0: zero stats + build weight layouts ----------
__global__ __launch_bounds__(256) void prep_kernel(
    const float* __restrict__ c1w, const float* __restrict__ c2w)
{
    int gid = blockIdx.x * 256 + threadIdx.x;
    int stride = gridDim.x * 256;
    if (gid < 64) { g_stats1[gid] = 0.f; g_stats2[gid] = 0.f; }
    // conv1 B fragments. k = a*120 + cb; cb = ci*10 + bphase; tap j = 10a + bphase.
    for (int i = gid; i < NCHUNK * 4 * 32; i += stride) {
        int lane = i & 31;
        int nt   = (i >> 5) & 3;
        int c    = i >> 7;
        int tig  = lane & 3;
        int g    = lane >> 2;
        int oc   = nt * 8 + g;
        int a    = c / 15;
        int cc   = c % 15;
        int cb0  = cc * 8 + tig;
        int cb1  = cb0 + 4;
        int ci0 = cb0 / 10, bp0 = cb0 % 10;
        int ci1 = cb1 / 10, bp1 = cb1 % 10;
        float w0 = c1w[(oc * CIN + ci0) * K1 + 10 * a + bp0];
        float w1 = c1w[(oc * CIN + ci1) * K1 + 10 * a + bp1];
        uint32_t h0, l0, h1, l1;
        tf32split(w0, h0, l0);
        tf32split(w1, h1, l1);
        g_B[i] = make_uint4(h0, h1, l0, l1);
    }
    // conv2: idx = (ci*25 + t)*32 + oc
    for (int i = gid; i < C2 * 25 * C2; i += stride) {
        int oc = i & 31;
        int rest = i >> 5;
        int t = rest % 25;
        int ci = rest / 25;
        g_w2s[i] = c2w[(oc * C2 + ci) * K2 + t];
    }
}

// ---------------- kernel 1: conv1 via 3xTF32 mma + BN1 stats ----------
// grid (8, 512): 64-position tiles. block 128 = 4 warps; warp wm owns rows
// [wm*16, wm*16+16) x all 32 oc. A pre-split into z_hi/z_lo at staging
// (inner loop = pure LDS + mma); B register-prefetched depth 2.
#define SMEM1_BYTES (2 * ZROWS * ZW * 4)   // 69120

__global__ __launch_bounds__(128) void conv1_kernel(
    const float* __restrict__ x, const float* __restrict__ bias)
{
    extern __shared__ uint32_t z_s[];
    uint32_t* zh = z_s;                 // tf32 hi bit patterns
    uint32_t* zl = z_s + ZROWS * ZW;    // tf32 lo bit patterns

    const int b     = blockIdx.y;
    const int tbase = blockIdx.x * 64;
    const int tid   = threadIdx.x;
    const int xstart = tbase * S1;

    // stage z[cb][p] = split(x[ci][xstart + 10p + bphase]), p in [0,68)
    for (int e = tid; e < ZROWS * 68; e += 128) {
        int cb = e / 68, p = e % 68;
        int ci = cb / 10, bp = cb % 10;
        int gp = xstart + 10 * p + bp;
        float v = (gp < LIN)
            ? __ldg(x + (size_t)(b * CIN + ci) * LIN + gp) : 0.f;
        uint32_t hi, lo;
        tf32split(v, hi, lo);
        zh[cb * ZW + p] = hi;
        zl[cb * ZW + p] = lo;
    }
    __syncthreads();

    const int lane = tid & 31;
    const int wm   = tid >> 5;
    const int tig  = lane & 3;
    const int g    = lane >> 2;

    float acc[4][4];
    #pragma unroll
    for (int nt = 0; nt < 4; nt++)
        #pragma unroll
        for (int k = 0; k < 4; k++) acc[nt][k] = 0.f;

    const uint4* gBl = g_B + lane;
    uint4 cur[4], pf1[4], pf2[4];
    #pragma unroll
    for (int nt = 0; nt < 4; nt++) {
        cur[nt] = __ldg(gBl + nt * 32);
        pf1[nt] = __ldg(gBl + 128 + nt * 32);
    }

    int c = 0;
    for (int a = 0; a < 5; a++) {
        int zoff = tig * ZW + wm * 16 + g + a;
        #pragma unroll 3
        for (int cc = 0; cc < 15; cc++) {
            // prefetch chunk c+2 (depth-2 ring)
            if (c < NCHUNK - 2) {
                const uint4* np = gBl + (size_t)(c + 2) * 128;
                #pragma unroll
                for (int nt = 0; nt < 4; nt++) pf2[nt] = __ldg(np + nt * 32);
            }
            // A fragments: pure conflict-free LDS (pre-split)
            uint32_t ah0 = zh[zoff];
            uint32_t ah1 = zh[zoff + 8];
            uint32_t ah2 = zh[zoff + 4 * ZW];
            uint32_t ah3 = zh[zoff + 4 * ZW + 8];
            uint32_t al0 = zl[zoff];
            uint32_t al1 = zl[zoff + 8];
            uint32_t al2 = zl[zoff + 4 * ZW];
            uint32_t al3 = zl[zoff + 4 * ZW + 8];
            #pragma unroll
            for (int nt = 0; nt < 4; nt++) {
                uint4 B = cur[nt];
                mma_tf32(acc[nt], ah0, ah1, ah2, ah3, B.x, B.y);  // hi*hi
                mma_tf32(acc[nt], ah0, ah1, ah2, ah3, B.z, B.w);  // hi*lo
                mma_tf32(acc[nt], al0, al1, al2, al3, B.x, B.y);  // lo*hi
            }
            #pragma unroll
            for (int nt = 0; nt < 4; nt++) { cur[nt] = pf1[nt]; pf1[nt] = pf2[nt]; }
            zoff += 8 * ZW;
            c++;
        }
    }

    // epilogue: bias, store, BN1 stats
    const int t0 = tbase + wm * 16 + g;
    const int t1 = t0 + 8;
    const bool ok0 = (t0 < L1);
    const bool ok1 = (t1 < L1);
    #pragma unroll
    for (int nt = 0; nt < 4; nt++) {
        int oce = nt * 8 + 2 * tig;
        int oco = oce + 1;
        float be = __ldg(bias + oce);
        float bo = __ldg(bias + oco);
        float v00 = acc[nt][0] + be;
        float v01 = acc[nt][1] + bo;
        float v10 = acc[nt][2] + be;
        float v11 = acc[nt][3] + bo;
        float* ye = g_y1 + ((size_t)b * C1 + oce) * L1;
        float* yo = g_y1 + ((size_t)b * C1 + oco) * L1;
        if (ok0) { ye[t0] = v00; yo[t0] = v01; }
        if (ok1) { ye[t1] = v10; yo[t1] = v11; }
        float se = (ok0 ? v00 : 0.f) + (ok1 ? v10 : 0.f);
        float qe = (ok0 ? v00 * v00 : 0.f) + (ok1 ? v10 * v10 : 0.f);
        float so = (ok0 ? v01 : 0.f) + (ok1 ? v11 : 0.f);
        float qo = (ok0 ? v01 * v01 : 0.f) + (ok1 ? v11 * v11 : 0.f);
        #pragma unroll
        for (int o = 4; o < 32; o <<= 1) {
            se += __shfl_xor_sync(0xffffffffu, se, o);
            qe += __shfl_xor_sync(0xffffffffu, qe, o);
            so += __shfl_xor_sync(0xffffffffu, so, o);
            qo += __shfl_xor_sync(0xffffffffu, qo, o);
        }
        if (g == 0) {
            atomicAdd(&g_stats1[oce], se);
            atomicAdd(&g_stats1[32 + oce], qe);
            atomicAdd(&g_stats1[oco], so);
            atomicAdd(&g_stats1[32 + oco], qo);
        }
    }
}

// ---------------- kernel 3: conv2 (BN1 finalize+relu fused) + BN2 stats
#define SMEM2_FLOATS (C2 * L1)            // 15872
#define SMEM2_BYTES  (SMEM2_FLOATS * 4)   // 63488
#define W2_SLICE4 200                     // float4 per ci slice (25*32 floats)

__global__ __launch_bounds__(256) void conv2_kernel(
    const float* __restrict__ bias,
    const float* __restrict__ bn1g, const float* __restrict__ bn1b)
{
    extern __shared__ float a_s[];        // [32][496]
    __shared__ __align__(16) float w_s[2][25 * C2];   // 2 x 3200 B
    __shared__ float bn1_s[64];

    const int b = blockIdx.x;
    const int tid = threadIdx.x;

    if (tid < 32) {
        const float invN = 1.f / (float)(BATCH * L1);
        float m = g_stats1[tid] * invN;
        float v = g_stats1[32 + tid] * invN - m * m;
        float sc = bn1g[tid] * rsqrtf(v + EPS);
        bn1_s[tid] = sc;
        bn1_s[32 + tid] = bn1b[tid] - m * sc;
    }
    const float4* wsrc = reinterpret_cast<const float4*>(g_w2s);
    if (tid < W2_SLICE4)
        reinterpret_cast<float4*>(w_s[0])[tid] = __ldg(wsrc + tid);
    __syncthreads();

    const float4* y1v = reinterpret_cast<const float4*>(g_y1 + (size_t)b * C2 * L1);
    float4* av = reinterpret_cast<float4*>(a_s);
    for (int i = tid; i < C2 * 124; i += 256) {
        int ci = i / 124;
        float sc = bn1_s[ci], sh = bn1_s[32 + ci];
        float4 v = __ldg(y1v + i);
        v.x = fmaxf(v.x * sc + sh, 0.f);
        v.y = fmaxf(v.y * sc + sh, 0.f);
        v.z = fmaxf(v.z * sc + sh, 0.f);
        v.w = fmaxf(v.w * sc + sh, 0.f);
        av[i] = v;
    }
    __syncthreads();

    const int lane = tid & 31;
    const int oc0  = (tid >> 5) * 4;
    const int p0 = lane * S2;
    const int p1 = p0 + 160;
    const bool ok2 = (lane + 64 < L2);
    const int p2 = ok2 ? p0 + 320 : 0;

    float acc[4][3];
    #pragma unroll
    for (int u = 0; u < 4; u++) { acc[u][0] = 0.f; acc[u][1] = 0.f; acc[u][2] = 0.f; }

    for (int ci = 0; ci < C2; ci++) {
        const int cur = ci & 1;
        const bool hasNext = (ci + 1 < C2);
        float4 pfv;
        if (hasNext && tid < W2_SLICE4)
            pfv = __ldg(wsrc + (ci + 1) * W2_SLICE4 + tid);

        const float* xr = a_s + ci * L1;
        const float* wr = w_s[cur] + oc0;
        #pragma unroll 5
        for (int t = 0; t < 25; t++) {
            float xA = xr[p0 + t];
            float xB = xr[p1 + t];
            float xC = xr[p2 + t];
            float4 wv = *reinterpret_cast<const float4*>(wr + t * C2);
            acc[0][0] += wv.x * xA; acc[0][1] += wv.x * xB; acc[0][2] += wv.x * xC;
            acc[1][0] += wv.y * xA; acc[1][1] += wv.y * xB; acc[1][2] += wv.y * xC;
            acc[2][0] += wv.z * xA; acc[2][1] += wv.z * xB; acc[2][2] += wv.z * xC;
            acc[3][0] += wv.w * xA; acc[3][1] += wv.w * xB; acc[3][2] += wv.w * xC;
        }

        if (hasNext) {
            __syncthreads();
            if (tid < W2_SLICE4)
                reinterpret_cast<float4*>(w_s[cur ^ 1])[tid] = pfv;
            __syncthreads();
        }
    }

    #pragma unroll
    for (int u = 0; u < 4; u++) {
        int oc = oc0 + u;
        float bsv = __ldg(bias + oc);
        float v0 = acc[u][0] + bsv;
        float v1 = acc[u][1] + bsv;
        float v2 = acc[u][2] + bsv;
        float* yo = g_y2 + ((size_t)b * C2 + oc) * L2;
        yo[lane] = v0;
        yo[lane + 32] = v1;
        if (ok2) yo[lane + 64] = v2;
        float s  = v0 + v1 + (ok2 ? v2 : 0.f);
        float s2 = v0 * v0 + v1 * v1 + (ok2 ? v2 * v2 : 0.f);
        s  = warp_sum(s);
        s2 = warp_sum(s2);
        if (lane == 0) {
            atomicAdd(&g_stats2[oc], s);
            atomicAdd(&g_stats2[32 + oc], s2);
        }
    }
}

// ---------------- kernel 4: BN2 finalize+relu, input projection, LN1 --
__global__ __launch_bounds__(256) void proj_kernel(
    const float* __restrict__ Wi, const float* __restrict__ bi,
    const float* __restrict__ ln1g, const float* __restrict__ ln1b,
    const float* __restrict__ bn2g, const float* __restrict__ bn2b)
{
    __shared__ float a_s[C2 * L2];
    __shared__ float Wi_s[32 * 33];
    __shared__ float bn2_s[64];

    const int b = blockIdx.x;
    const int tid = threadIdx.x;

    if (tid < 32) {
        const float invN = 1.f / (float)(BATCH * L2);
        float m = g_stats2[tid] * invN;
        float v = g_stats2[32 + tid] * invN - m * m;
        float sc = bn2g[tid] * rsqrtf(v + EPS);
        bn2_s[tid] = sc;
        bn2_s[32 + tid] = bn2b[tid] - m * sc;
    }
    __syncthreads();

    for (int i = tid; i < C2 * L2; i += 256) {
        int c = i / L2;
        float v = g_y2[(size_t)b * C2 * L2 + i];
        a_s[i] = fmaxf(v * bn2_s[c] + bn2_s[32 + c], 0.f);
    }
    for (int i = tid; i < 32 * 32; i += 256)
        Wi_s[(i >> 5) * 33 + (i & 31)] = Wi[i];
    __syncthreads();

    const int lane = tid & 31;
    const int wp = tid >> 5;
    const float biv = bi[lane];
    const float gv = ln1g[lane], bv = ln1b[lane];

    for (int t = wp; t < L2; t += 8) {
        float z = biv;
        #pragma unroll
        for (int c = 0; c < 32; c++)
            z += Wi_s[lane * 33 + c] * a_s[c * L2 + t];
        float m = warp_sum(z) * (1.f / 32.f);
        float d = z - m;
        float var = warp_sum(d * d) * (1.f / 32.f);
        float r = rsqrtf(var + EPS);
        g_xt[((size_t)t * BATCH + b) * LAT + lane] = d * r * gv + bv;
    }
}

// ---------------- kernel 5: recurrent scan + pool + output proj -------
__global__ __launch_bounds__(128) void rnn_kernel(
    const float* __restrict__ Wh, const float* __restrict__ bh,
    const float* __restrict__ ln2g, const float* __restrict__ ln2b,
    const float* __restrict__ Wr, const float* __restrict__ br,
    const float* __restrict__ Wo, const float* __restrict__ bo,
    float* __restrict__ out)
{
    __shared__ float Wh_s[64 * 33];
    __shared__ float Wr_s[32 * 65];
    __shared__ float Wo_s[32 * 33];

    const int tid = threadIdx.x;
    const int lane = tid & 31;
    const int wp = tid >> 5;
    for (int i = tid; i < 64 * 32; i += 128) Wh_s[(i >> 5) * 33 + (i & 31)] = Wh[i];
    for (int i = tid; i < 32 * 64; i += 128) Wr_s[(i / 64) * 65 + (i % 64)] = Wr[i];
    for (int i = tid; i < 32 * 32; i += 128) Wo_s[(i >> 5) * 33 + (i & 31)] = Wo[i];
    __syncthreads();

    const int b = blockIdx.x * 4 + wp;
    const float bh0 = bh[lane], bh1 = bh[lane + 32];
    const float gA = ln2g[lane], bA = ln2b[lane];
    const float gB = ln2g[lane + 32], bB = ln2b[lane + 32];
    const float brl = br[lane];

    float h = 0.f, psum = 0.f;
    for (int t = 0; t < TSTEPS; t++) {
        float c = g_xt[((size_t)t * BATCH + b) * LAT + lane] + h;
        float a0a = bh0, a0b = 0.f, a1a = bh1, a1b = 0.f;
        #pragma unroll
        for (int j = 0; j < 32; j += 2) {
            float cj0 = __shfl_sync(0xffffffffu, c, j);
            float cj1 = __shfl_sync(0xffffffffu, c, j + 1);
            a0a += Wh_s[lane * 33 + j] * cj0;
            a0b += Wh_s[lane * 33 + j + 1] * cj1;
            a1a += Wh_s[(lane + 32) * 33 + j] * cj0;
            a1b += Wh_s[(lane + 32) * 33 + j + 1] * cj1;
        }
        float a0 = fmaxf(a0a + a0b, 0.f);
        float a1 = fmaxf(a1a + a1b, 0.f);
        float m = warp_sum(a0 + a1) * (1.f / 64.f);
        float d0 = a0 - m, d1 = a1 - m;
        float var = warp_sum(d0 * d0 + d1 * d1) * (1.f / 64.f);
        float r = rsqrtf(var + EPS);
        float n0 = d0 * r * gA + bA;
        float n1 = d1 * r * gB + bB;
        float acca = brl, accb = 0.f;
        #pragma unroll
        for (int i = 0; i < 32; i++) {
            float v0 = __shfl_sync(0xffffffffu, n0, i);
            float v1 = __shfl_sync(0xffffffffu, n1, i);
            acca += Wr_s[lane * 65 + i] * v0;
            accb += Wr_s[lane * 65 + 32 + i] * v1;
        }
        h = tanhf(acca + accb);
        psum += h;
    }
    float p = psum * (1.f / (float)TSTEPS);
    float o = bo[lane];
    #pragma unroll
    for (int j = 0; j < 32; j++)
        o += Wo_s[lane * 33 + j] * __shfl_sync(0xffffffffu, p, j);
    out[b * 32 + lane] = o;
}

// ---------------- launch ----------------
extern "C" void kernel_launch(void* const* d_in, const int* in_sizes, int n_in,
                              void* d_out, int out_size)
{
    const float* x    = (const float*)d_in[0];
    const float* c1w  = (const float*)d_in[1];
    const float* c1b  = (const float*)d_in[2];
    const float* bn1g = (const float*)d_in[3];
    const float* bn1b = (const float*)d_in[4];
    const float* c2w  = (const float*)d_in[5];
    const float* c2b  = (const float*)d_in[6];
    const float* bn2g = (const float*)d_in[7];
    const float* bn2b = (const float*)d_in[8];
    const float* Wi   = (const float*)d_in[9];
    const float* bi   = (const float*)d_in[10];
    const float* ln1g = (const float*)d_in[11];
    const float* ln1b = (const float*)d_in[12];
    const float* Wh   = (const float*)d_in[13];
    const float* bh   = (const float*)d_in[14];
    const float* ln2g = (const float*)d_in[15];
    const float* ln2b = (const float*)d_in[16];
    const float* Wr   = (const float*)d_in[17];
    const float* br   = (const float*)d_in[18];
    const float* Wo   = (const float*)d_in[19];
    const float* bo   = (const float*)d_in[20];
    float* out = (float*)d_out;

    static bool attr_done = false;
    if (!attr_done) {
        cudaFuncSetAttribute(conv1_kernel, cudaFuncAttributeMaxDynamicSharedMemorySize, SMEM1_BYTES);
        cudaFuncSetAttribute(conv2_kernel, cudaFuncAttributeMaxDynamicSharedMemorySize, SMEM2_BYTES);
        attr_done = true;
    }

    prep_kernel<<<64, 256>>>(c1w, c2w);
    conv1_kernel<<<dim3(8, BATCH), 128, SMEM1_BYTES>>>(x, c1b);
    conv2_kernel<<<BATCH, 256, SMEM2_BYTES>>>(c2b, bn1g, bn1b);
    proj_kernel<<<BATCH, 256>>>(Wi, bi, ln1g, ln1b, bn2g, bn2b);
    rnn_kernel<<<BATCH / 4, 128>>>(Wh, bh, ln2g, ln2b, Wr, br, Wo, bo, out);
}

// round 17
// speedup vs baseline: 1.2130x; 1.2130x over previous
#include <cuda_runtime.h>
#include <cuda_bf16.h>
#include <cstdint>

#define BATCH 512
#define CIN   12
#define LIN   5000
#define C1    32
#define K1    50
#define S1    10
#define L1    496
#define C2    32
#define K2    25
#define S2    5
#define L2    95
#define LAT   32
#define HID   64
#define TSTEPS L2
#define EPS   1e-5f

// conv1 bf16 implicit GEMM: K = 600 = 5(a) * 120(cb), padded to 128 cb rows.
// 8 K16-chunks per a (7 real + 1 half-padded) -> 40 chunks total.
#define NCH1  40
#define ZPW   72            // zp row stride (uint32 entries); 72 mod 32 = 8
#define ZPROWS 64           // cb-pair rows (cb 0..127 / 2)

// ---------------- device scratch (no allocation allowed) ----------------
// conv1 B fragments: [chunk(40)][ntile(4)][lane(32)] = {bhi0,bhi1,blo0,blo1}
__device__ __align__(16) uint4 g_B[NCH1 * 4 * 32];
// conv2 weights: [ci][tap(25)][oc(32)] float
__device__ __align__(16) float g_w2s[C2 * 25 * C2];
__device__ float g_y1[BATCH * C1 * L1];
__device__ float g_y2[BATCH * C2 * L2];
__device__ float g_xt[TSTEPS * BATCH * LAT];
__device__ float g_stats1[64];
__device__ float g_stats2[64];

__device__ __forceinline__ float warp_sum(float v) {
    #pragma unroll
    for (int o = 16; o; o >>= 1) v += __shfl_xor_sync(0xffffffffu, v, o);
    return v;
}
__device__ __forceinline__ void bf16split(float x, uint32_t& h, uint32_t& l) {
    __nv_bfloat16 bh = __float2bfloat16(x);
    float r = x - __bfloat162float(bh);
    __nv_bfloat16 bl = __float2bfloat16(r);
    h = (uint32_t)__bfloat16_as_ushort(bh);
    l = (uint32_t)__bfloat16_as_ushort(bl);
}
__device__ __forceinline__ uint32_t pack16(uint32_t lo, uint32_t hi) {
    return lo | (hi << 16);
}
__device__ __forceinline__ void mma_bf16(float* d,
    uint32_t a0, uint32_t a1, uint32_t a2, uint32_t a3,
    uint32_t b0, uint32_t b1)
{
    asm volatile(
        "mma.sync.aligned.m16n8k16.row.col.f32.bf16.bf16.f32 "
        "{%0,%1,%2,%3},{%4,%5,%6,%7},{%8,%9},{%0,%1,%2,%3};"
        : "+f"(d[0]), "+f"(d[1]), "+f"(d[2]), "+f"(d[3])
        : "r"(a0), "r"(a1), "r"(a2), "r"(a3), "r"(b0), "r"(b1));
}

// ---------------- kernel 0: zero stats + build weight layouts ----------
__global__ __launch_bounds__(256) void prep_kernel(
    const float* __restrict__ c1w, const float* __restrict__ c2w)
{
    int gid = blockIdx.x * 256 + threadIdx.x;
    int stride = gridDim.x * 256;
    if (gid < 64) { g_stats1[gid] = 0.f; g_stats2[gid] = 0.f; }
    // conv1 B fragments. chunk c: a = c>>3, cc = c&7, cb = cc*16 + j (j=0..15).
    // lane (g = lane>>2, tig = lane&3); oc = nt*8 + g.
    // b0 = {B[j=2tig], B[j=2tig+1]}, b1 = {B[j=2tig+8], B[j=2tig+9]}.
    for (int i = gid; i < NCH1 * 4 * 32; i += stride) {
        int lane = i & 31;
        int nt   = (i >> 5) & 3;
        int c    = i >> 7;
        int tig  = lane & 3;
        int g    = lane >> 2;
        int oc   = nt * 8 + g;
        int a    = c >> 3;
        int cc   = c & 7;
        uint32_t h[4], l[4];
        #pragma unroll
        for (int e = 0; e < 4; e++) {
            int j  = (e < 2) ? (2 * tig + e) : (2 * tig + 8 + (e - 2));
            int cb = cc * 16 + j;
            float w = 0.f;
            if (cb < 120) {
                int ci = cb / 10, bp = cb % 10;
                w = c1w[(oc * CIN + ci) * K1 + 10 * a + bp];
            }
            bf16split(w, h[e], l[e]);
        }
        g_B[i] = make_uint4(pack16(h[0], h[1]), pack16(h[2], h[3]),
                            pack16(l[0], l[1]), pack16(l[2], l[3]));
    }
    // conv2: idx = (ci*25 + t)*32 + oc
    for (int i = gid; i < C2 * 25 * C2; i += stride) {
        int oc = i & 31;
        int rest = i >> 5;
        int t = rest % 25;
        int ci = rest / 25;
        g_w2s[i] = c2w[(oc * C2 + ci) * K2 + t];
    }
}

// ---------------- kernel 1: conv1 via 3xBF16 mma + BN1 stats ----------
// grid (8, 512): 64-position tiles. block 128 = 4 warps; warp wm owns rows
// [wm*16, wm*16+16) x all 32 oc. z packed as bf16x2 cb-pairs (hi/lo planes).
__global__ __launch_bounds__(128) void conv1_kernel(
    const float* __restrict__ x, const float* __restrict__ bias)
{
    __shared__ uint32_t zph[ZPROWS * ZPW];   // 18432 B
    __shared__ uint32_t zpl[ZPROWS * ZPW];   // 18432 B

    const int b     = blockIdx.y;
    const int tbase = blockIdx.x * 64;
    const int tid   = threadIdx.x;
    const int xstart = tbase * S1;

    // stage zp[cbp][p] = bf16x2{ split(z[2cbp][p]), split(z[2cbp+1][p]) }
    // z[cb][p] = x[ci][xstart + 10p + bp], p in [0,68); rows cbp>=60 zero.
    for (int e = tid; e < ZPROWS * 68; e += 128) {
        int cbp = e / 68, p = e % 68;
        uint32_t hv = 0, lv = 0;
        if (cbp < 60) {
            int cb0 = 2 * cbp, cb1 = 2 * cbp + 1;
            int ci0 = cb0 / 10, bp0 = cb0 % 10;
            int ci1 = cb1 / 10, bp1 = cb1 % 10;
            int gp0 = xstart + 10 * p + bp0;
            int gp1 = xstart + 10 * p + bp1;
            float v0 = (gp0 < LIN) ? __ldg(x + (size_t)(b * CIN + ci0) * LIN + gp0) : 0.f;
            float v1 = (gp1 < LIN) ? __ldg(x + (size_t)(b * CIN + ci1) * LIN + gp1) : 0.f;
            uint32_t h0, l0, h1, l1;
            bf16split(v0, h0, l0);
            bf16split(v1, h1, l1);
            hv = pack16(h0, h1);
            lv = pack16(l0, l1);
        }
        zph[cbp * ZPW + p] = hv;
        zpl[cbp * ZPW + p] = lv;
    }
    __syncthreads();

    const int lane = tid & 31;
    const int wm   = tid >> 5;
    const int tig  = lane & 3;
    const int g    = lane >> 2;

    float acc[4][4];
    #pragma unroll
    for (int nt = 0; nt < 4; nt++)
        #pragma unroll
        for (int k = 0; k < 4; k++) acc[nt][k] = 0.f;

    const uint4* gBl = g_B + lane;
    uint4 cur[4], pf[4];
    #pragma unroll
    for (int nt = 0; nt < 4; nt++) cur[nt] = __ldg(gBl + nt * 32);

    int c = 0;
    for (int a = 0; a < 5; a++) {
        // base address: row = tig (cb-pair within chunk), col = t + a
        int zoff = tig * ZPW + wm * 16 + g + a;
        #pragma unroll 2
        for (int cc = 0; cc < 8; cc++) {
            if (c < NCH1 - 1) {
                const uint4* np = gBl + (size_t)(c + 1) * 128;
                #pragma unroll
                for (int nt = 0; nt < 4; nt++) pf[nt] = __ldg(np + nt * 32);
            }
            // A fragments: conflict-free LDS (hi/lo planes, pre-packed bf16x2)
            uint32_t ah0 = zph[zoff];
            uint32_t ah1 = zph[zoff + 8];
            uint32_t ah2 = zph[zoff + 4 * ZPW];
            uint32_t ah3 = zph[zoff + 4 * ZPW + 8];
            uint32_t al0 = zpl[zoff];
            uint32_t al1 = zpl[zoff + 8];
            uint32_t al2 = zpl[zoff + 4 * ZPW];
            uint32_t al3 = zpl[zoff + 4 * ZPW + 8];
            #pragma unroll
            for (int nt = 0; nt < 4; nt++) {
                uint4 B = cur[nt];
                mma_bf16(acc[nt], ah0, ah1, ah2, ah3, B.x, B.y);  // hi*hi
                mma_bf16(acc[nt], ah0, ah1, ah2, ah3, B.z, B.w);  // hi*lo
                mma_bf16(acc[nt], al0, al1, al2, al3, B.x, B.y);  // lo*hi
            }
            #pragma unroll
            for (int nt = 0; nt < 4; nt++) cur[nt] = pf[nt];
            zoff += 8 * ZPW;   // 8 cb-pair rows = 16 cb per chunk
            c++;
        }
    }

    // epilogue: bias, store, BN1 stats (D: c0=(g,2tig), c1=(g,2tig+1), ...)
    const int t0 = tbase + wm * 16 + g;
    const int t1 = t0 + 8;
    const bool ok0 = (t0 < L1);
    const bool ok1 = (t1 < L1);
    #pragma unroll
    for (int nt = 0; nt < 4; nt++) {
        int oce = nt * 8 + 2 * tig;
        int oco = oce + 1;
        float be = __ldg(bias + oce);
        float bo = __ldg(bias + oco);
        float v00 = acc[nt][0] + be;
        float v01 = acc[nt][1] + bo;
        float v10 = acc[nt][2] + be;
        float v11 = acc[nt][3] + bo;
        float* ye = g_y1 + ((size_t)b * C1 + oce) * L1;
        float* yo = g_y1 + ((size_t)b * C1 + oco) * L1;
        if (ok0) { ye[t0] = v00; yo[t0] = v01; }
        if (ok1) { ye[t1] = v10; yo[t1] = v11; }
        float se = (ok0 ? v00 : 0.f) + (ok1 ? v10 : 0.f);
        float qe = (ok0 ? v00 * v00 : 0.f) + (ok1 ? v10 * v10 : 0.f);
        float so = (ok0 ? v01 : 0.f) + (ok1 ? v11 : 0.f);
        float qo = (ok0 ? v01 * v01 : 0.f) + (ok1 ? v11 * v11 : 0.f);
        #pragma unroll
        for (int o = 4; o < 32; o <<= 1) {
            se += __shfl_xor_sync(0xffffffffu, se, o);
            qe += __shfl_xor_sync(0xffffffffu, qe, o);
            so += __shfl_xor_sync(0xffffffffu, so, o);
            qo += __shfl_xor_sync(0xffffffffu, qo, o);
        }
        if (g == 0) {
            atomicAdd(&g_stats1[oce], se);
            atomicAdd(&g_stats1[32 + oce], qe);
            atomicAdd(&g_stats1[oco], so);
            atomicAdd(&g_stats1[32 + oco], qo);
        }
    }
}

// ---------------- kernel 3: conv2 (BN1 finalize+relu fused) + BN2 stats
#define SMEM2_FLOATS (C2 * L1)            // 15872
#define SMEM2_BYTES  (SMEM2_FLOATS * 4)   // 63488
#define W2_SLICE4 200                     // float4 per ci slice (25*32 floats)

__global__ __launch_bounds__(256) void conv2_kernel(
    const float* __restrict__ bias,
    const float* __restrict__ bn1g, const float* __restrict__ bn1b)
{
    extern __shared__ float a_s[];        // [32][496]
    __shared__ __align__(16) float w_s[2][25 * C2];   // 2 x 3200 B
    __shared__ float bn1_s[64];

    const int b = blockIdx.x;
    const int tid = threadIdx.x;

    if (tid < 32) {
        const float invN = 1.f / (float)(BATCH * L1);
        float m = g_stats1[tid] * invN;
        float v = g_stats1[32 + tid] * invN - m * m;
        float sc = bn1g[tid] * rsqrtf(v + EPS);
        bn1_s[tid] = sc;
        bn1_s[32 + tid] = bn1b[tid] - m * sc;
    }
    const float4* wsrc = reinterpret_cast<const float4*>(g_w2s);
    if (tid < W2_SLICE4)
        reinterpret_cast<float4*>(w_s[0])[tid] = __ldg(wsrc + tid);
    __syncthreads();

    const float4* y1v = reinterpret_cast<const float4*>(g_y1 + (size_t)b * C2 * L1);
    float4* av = reinterpret_cast<float4*>(a_s);
    for (int i = tid; i < C2 * 124; i += 256) {
        int ci = i / 124;
        float sc = bn1_s[ci], sh = bn1_s[32 + ci];
        float4 v = __ldg(y1v + i);
        v.x = fmaxf(v.x * sc + sh, 0.f);
        v.y = fmaxf(v.y * sc + sh, 0.f);
        v.z = fmaxf(v.z * sc + sh, 0.f);
        v.w = fmaxf(v.w * sc + sh, 0.f);
        av[i] = v;
    }
    __syncthreads();

    const int lane = tid & 31;
    const int oc0  = (tid >> 5) * 4;
    const int p0 = lane * S2;
    const int p1 = p0 + 160;
    const bool ok2 = (lane + 64 < L2);
    const int p2 = ok2 ? p0 + 320 : 0;

    float acc[4][3];
    #pragma unroll
    for (int u = 0; u < 4; u++) { acc[u][0] = 0.f; acc[u][1] = 0.f; acc[u][2] = 0.f; }

    for (int ci = 0; ci < C2; ci++) {
        const int cur = ci & 1;
        const bool hasNext = (ci + 1 < C2);
        float4 pfv;
        if (hasNext && tid < W2_SLICE4)
            pfv = __ldg(wsrc + (ci + 1) * W2_SLICE4 + tid);

        const float* xr = a_s + ci * L1;
        const float* wr = w_s[cur] + oc0;
        #pragma unroll 5
        for (int t = 0; t < 25; t++) {
            float xA = xr[p0 + t];
            float xB = xr[p1 + t];
            float xC = xr[p2 + t];
            float4 wv = *reinterpret_cast<const float4*>(wr + t * C2);
            acc[0][0] += wv.x * xA; acc[0][1] += wv.x * xB; acc[0][2] += wv.x * xC;
            acc[1][0] += wv.y * xA; acc[1][1] += wv.y * xB; acc[1][2] += wv.y * xC;
            acc[2][0] += wv.z * xA; acc[2][1] += wv.z * xB; acc[2][2] += wv.z * xC;
            acc[3][0] += wv.w * xA; acc[3][1] += wv.w * xB; acc[3][2] += wv.w * xC;
        }

        if (hasNext) {
            __syncthreads();
            if (tid < W2_SLICE4)
                reinterpret_cast<float4*>(w_s[cur ^ 1])[tid] = pfv;
            __syncthreads();
        }
    }

    #pragma unroll
    for (int u = 0; u < 4; u++) {
        int oc = oc0 + u;
        float bsv = __ldg(bias + oc);
        float v0 = acc[u][0] + bsv;
        float v1 = acc[u][1] + bsv;
        float v2 = acc[u][2] + bsv;
        float* yo = g_y2 + ((size_t)b * C2 + oc) * L2;
        yo[lane] = v0;
        yo[lane + 32] = v1;
        if (ok2) yo[lane + 64] = v2;
        float s  = v0 + v1 + (ok2 ? v2 : 0.f);
        float s2 = v0 * v0 + v1 * v1 + (ok2 ? v2 * v2 : 0.f);
        s  = warp_sum(s);
        s2 = warp_sum(s2);
        if (lane == 0) {
            atomicAdd(&g_stats2[oc], s);
            atomicAdd(&g_stats2[32 + oc], s2);
        }
    }
}

// ---------------- kernel 4: BN2 finalize+relu, input projection, LN1 --
__global__ __launch_bounds__(256) void proj_kernel(
    const float* __restrict__ Wi, const float* __restrict__ bi,
    const float* __restrict__ ln1g, const float* __restrict__ ln1b,
    const float* __restrict__ bn2g, const float* __restrict__ bn2b)
{
    __shared__ float a_s[C2 * L2];
    __shared__ float Wi_s[32 * 33];
    __shared__ float bn2_s[64];

    const int b = blockIdx.x;
    const int tid = threadIdx.x;

    if (tid < 32) {
        const float invN = 1.f / (float)(BATCH * L2);
        float m = g_stats2[tid] * invN;
        float v = g_stats2[32 + tid] * invN - m * m;
        float sc = bn2g[tid] * rsqrtf(v + EPS);
        bn2_s[tid] = sc;
        bn2_s[32 + tid] = bn2b[tid] - m * sc;
    }
    __syncthreads();

    for (int i = tid; i < C2 * L2; i += 256) {
        int c = i / L2;
        float v = g_y2[(size_t)b * C2 * L2 + i];
        a_s[i] = fmaxf(v * bn2_s[c] + bn2_s[32 + c], 0.f);
    }
    for (int i = tid; i < 32 * 32; i += 256)
        Wi_s[(i >> 5) * 33 + (i & 31)] = Wi[i];
    __syncthreads();

    const int lane = tid & 31;
    const int wp = tid >> 5;
    const float biv = bi[lane];
    const float gv = ln1g[lane], bv = ln1b[lane];

    for (int t = wp; t < L2; t += 8) {
        float z = biv;
        #pragma unroll
        for (int c = 0; c < 32; c++)
            z += Wi_s[lane * 33 + c] * a_s[c * L2 + t];
        float m = warp_sum(z) * (1.f / 32.f);
        float d = z - m;
        float var = warp_sum(d * d) * (1.f / 32.f);
        float r = rsqrtf(var + EPS);
        g_xt[((size_t)t * BATCH + b) * LAT + lane] = d * r * gv + bv;
    }
}

// ---------------- kernel 5: recurrent scan + pool + output proj -------
__global__ __launch_bounds__(128) void rnn_kernel(
    const float* __restrict__ Wh, const float* __restrict__ bh,
    const float* __restrict__ ln2g, const float* __restrict__ ln2b,
    const float* __restrict__ Wr, const float* __restrict__ br,
    const float* __restrict__ Wo, const float* __restrict__ bo,
    float* __restrict__ out)
{
    __shared__ float Wh_s[64 * 33];
    __shared__ float Wr_s[32 * 65];
    __shared__ float Wo_s[32 * 33];

    const int tid = threadIdx.x;
    const int lane = tid & 31;
    const int wp = tid >> 5;
    for (int i = tid; i < 64 * 32; i += 128) Wh_s[(i >> 5) * 33 + (i & 31)] = Wh[i];
    for (int i = tid; i < 32 * 64; i += 128) Wr_s[(i / 64) * 65 + (i % 64)] = Wr[i];
    for (int i = tid; i < 32 * 32; i += 128) Wo_s[(i >> 5) * 33 + (i & 31)] = Wo[i];
    __syncthreads();

    const int b = blockIdx.x * 4 + wp;
    const float bh0 = bh[lane], bh1 = bh[lane + 32];
    const float gA = ln2g[lane], bA = ln2b[lane];
    const float gB = ln2g[lane + 32], bB = ln2b[lane + 32];
    const float brl = br[lane];

    float h = 0.f, psum = 0.f;
    for (int t = 0; t < TSTEPS; t++) {
        float c = g_xt[((size_t)t * BATCH + b) * LAT + lane] + h;
        float a0a = bh0, a0b = 0.f, a1a = bh1, a1b = 0.f;
        #pragma unroll
        for (int j = 0; j < 32; j += 2) {
            float cj0 = __shfl_sync(0xffffffffu, c, j);
            float cj1 = __shfl_sync(0xffffffffu, c, j + 1);
            a0a += Wh_s[lane * 33 + j] * cj0;
            a0b += Wh_s[lane * 33 + j + 1] * cj1;
            a1a += Wh_s[(lane + 32) * 33 + j] * cj0;
            a1b += Wh_s[(lane + 32) * 33 + j + 1] * cj1;
        }
        float a0 = fmaxf(a0a + a0b, 0.f);
        float a1 = fmaxf(a1a + a1b, 0.f);
        float m = warp_sum(a0 + a1) * (1.f / 64.f);
        float d0 = a0 - m, d1 = a1 - m;
        float var = warp_sum(d0 * d0 + d1 * d1) * (1.f / 64.f);
        float r = rsqrtf(var + EPS);
        float n0 = d0 * r * gA + bA;
        float n1 = d1 * r * gB + bB;
        float acca = brl, accb = 0.f;
        #pragma unroll
        for (int i = 0; i < 32; i++) {
            float v0 = __shfl_sync(0xffffffffu, n0, i);
            float v1 = __shfl_sync(0xffffffffu, n1, i);
            acca += Wr_s[lane * 65 + i] * v0;
            accb += Wr_s[lane * 65 + 32 + i] * v1;
        }
        h = tanhf(acca + accb);
        psum += h;
    }
    float p = psum * (1.f / (float)TSTEPS);
    float o = bo[lane];
    #pragma unroll
    for (int j = 0; j < 32; j++)
        o += Wo_s[lane * 33 + j] * __shfl_sync(0xffffffffu, p, j);
    out[b * 32 + lane] = o;
}

// ---------------- launch ----------------
extern "C" void kernel_launch(void* const* d_in, const int* in_sizes, int n_in,
                              void* d_out, int out_size)
{
    const float* x    = (const float*)d_in[0];
    const float* c1w  = (const float*)d_in[1];
    const float* c1b  = (const float*)d_in[2];
    const float* bn1g = (const float*)d_in[3];
    const float* bn1b = (const float*)d_in[4];
    const float* c2w  = (const float*)d_in[5];
    const float* c2b  = (const float*)d_in[6];
    const float* bn2g = (const float*)d_in[7];
    const float* bn2b = (const float*)d_in[8];
    const float* Wi   = (const float*)d_in[9];
    const float* bi   = (const float*)d_in[10];
    const float* ln1g = (const float*)d_in[11];
    const float* ln1b = (const float*)d_in[12];
    const float* Wh   = (const float*)d_in[13];
    const float* bh   = (const float*)d_in[14];
    const float* ln2g = (const float*)d_in[15];
    const float* ln2b = (const float*)d_in[16];
    const float* Wr   = (const float*)d_in[17];
    const float* br   = (const float*)d_in[18];
    const float* Wo   = (const float*)d_in[19];
    const float* bo   = (const float*)d_in[20];
    float* out = (float*)d_out;

    static bool attr_done = false;
    if (!attr_done) {
        cudaFuncSetAttribute(conv2_kernel, cudaFuncAttributeMaxDynamicSharedMemorySize, SMEM2_BYTES);
        attr_done = true;
    }

    prep_kernel<<<64, 256>>>(c1w, c2w);
    conv1_kernel<<<dim3(8, BATCH), 128>>>(x, c1b);
    conv2_kernel<<<BATCH, 256, SMEM2_BYTES>>>(c2b, bn1g, bn1b);
    proj_kernel<<<BATCH, 256>>>(Wi, bi, ln1g, ln1b, bn2g, bn2b);
    rnn_kernel<<<BATCH / 4, 128>>>(Wh, bh, ln2g, ln2b, Wr, br, Wo, bo, out);
}